// round 7
// baseline (speedup 1.0000x reference)
#include <cuda_runtime.h>
#include <cuda_bf16.h>
#include <mma.h>
#include <cstdint>
#include <math.h>

using namespace nvcuda;

// ----------------------------------------------------------------------------
// Problem constants
// ----------------------------------------------------------------------------
#define S_DIM   2048
#define B_DIM   16
#define H2_DIM  2048
#define V_DIM   1024
#define M_DIM   (S_DIM * B_DIM)          // 32768
#define K_TOT   (2 * H2_DIM)             // 4096
#define ALPHA_S 0.5f

// ----------------------------------------------------------------------------
// GEMM tiling
// ----------------------------------------------------------------------------
#define MT 128
#define NTILE 128
#define KT 32
#define NCHUNK  (K_TOT / KT)             // 128
#define NTILES  (V_DIM / NTILE)          // 8
#define MTILES  (M_DIM / MT)             // 256
#define STAGES  3

// SMEM strides (floats), padded to multiple of 8 for wmma + conflict relief
#define A_STRIDE 40                      // 32 + 8
#define B_STRIDE 136                     // 128 + 8
#define C_STRIDE 136

#define A_STAGE_FLOATS (MT * A_STRIDE)               // 5120
#define B_STAGE_FLOATS (KT * B_STRIDE)               // 4352
#define STAGE_FLOATS   (A_STAGE_FLOATS + B_STAGE_FLOATS)   // 9472
#define STAGE_AREA_FLOATS (STAGES * STAGE_FLOATS)    // 28416
#define BIAS_OFF  STAGE_AREA_FLOATS                  // floats
#define VW_OFF    (BIAS_OFF + NTILE)
#define SMEM_FLOATS (VW_OFF + NTILE)                 // 28672
#define SMEM_BYTES (SMEM_FLOATS * 4)                 // 114688

// ----------------------------------------------------------------------------
// Device scratch (static — no runtime allocation)
// ----------------------------------------------------------------------------
__device__ __align__(128) float g_part[NTILES * M_DIM];   // 1 MB partial u

// ----------------------------------------------------------------------------
// cp.async helpers (sm_80+, valid on compute_103)
// ----------------------------------------------------------------------------
__device__ __forceinline__ uint32_t smem_u32(const void* p) {
    uint32_t a;
    asm("{ .reg .u64 t; cvta.to.shared.u64 t, %1; cvt.u32.u64 %0, t; }" : "=r"(a) : "l"(p));
    return a;
}
__device__ __forceinline__ void cp_async16(uint32_t dst, const void* src) {
    asm volatile("cp.async.cg.shared.global [%0], [%1], 16;" :: "r"(dst), "l"(src) : "memory");
}
#define CP_COMMIT_GROUP()  asm volatile("cp.async.commit_group;" ::: "memory")
#define CP_WAIT_GROUP(n)   asm volatile("cp.async.wait_group %0;" :: "n"(n) : "memory")
#define CP_WAIT_ALL()      asm volatile("cp.async.wait_all;" ::: "memory")

// ----------------------------------------------------------------------------
// Stage fill: A tile [128 x 32] from hidden|z, B tile [32 x 128] from Ww|Wz
// 256 threads, 4 + 4 cp.async(16B) per thread.
// ----------------------------------------------------------------------------
__device__ __forceinline__ void fill_stage(
    float* smemf, uint32_t smem_base, int s, int kc,
    const float* __restrict__ hidden, const float* __restrict__ z,
    const float* __restrict__ Ww, const float* __restrict__ Wz,
    int mtile, int ntile, int tid)
{
    const int k0 = kc * KT;                     // global K offset (0..4095)
    uint32_t aBase = smem_base + (uint32_t)(s * STAGE_FLOATS) * 4u;
    uint32_t bBase = aBase + (uint32_t)A_STAGE_FLOATS * 4u;

    // A: 128 rows x 8 chunks(16B) = 1024 chunks
    {
        const float* abase = (k0 < H2_DIM) ? (hidden + k0) : (z + (k0 - H2_DIM));
#pragma unroll
        for (int i = 0; i < 4; i++) {
            int idx = tid + i * 256;
            int r = idx >> 3, g = idx & 7;
            const float* src = abase + (size_t)(mtile * MT + r) * H2_DIM + g * 4;
            uint32_t dst = aBase + (uint32_t)(r * A_STRIDE + g * 4) * 4u;
            cp_async16(dst, src);
        }
    }
    // B: 32 rows x 32 chunks(16B) = 1024 chunks
    {
        const float* bbase = (k0 < H2_DIM) ? (Ww + (size_t)k0 * V_DIM)
                                           : (Wz + (size_t)(k0 - H2_DIM) * V_DIM);
#pragma unroll
        for (int i = 0; i < 4; i++) {
            int idx = tid + i * 256;
            int r = idx >> 5, c = idx & 31;
            const float* src = bbase + (size_t)r * V_DIM + ntile * NTILE + c * 4;
            uint32_t dst = bBase + (uint32_t)(r * B_STRIDE + c * 4) * 4u;
            cp_async16(dst, src);
        }
    }
    CP_COMMIT_GROUP();
    (void)smemf;
}

// ----------------------------------------------------------------------------
// Kernel 1: fused tf32 GEMM + tanh-dot epilogue -> g_part[ntile][m]
// ----------------------------------------------------------------------------
__global__ void __launch_bounds__(256, 1)
dual_attn_gemm_kernel(const float* __restrict__ hidden, const float* __restrict__ z,
                      const float* __restrict__ Ww,     const float* __restrict__ Wz,
                      const float* __restrict__ bw,     const float* __restrict__ bz,
                      const float* __restrict__ Vw,     const float* __restrict__ w_a)
{
    extern __shared__ float smemf[];
    uint32_t smem_base = smem_u32(smemf);
    const int tid = threadIdx.x;
    const int wid = tid >> 5;
    const int ntile = blockIdx.x;   // 0..7  (varies fastest -> B stays in L2)
    const int mtile = blockIdx.y;   // 0..255

    // Warp layout: 4 x 2 warps; warp tile = 32 (M) x 64 (N)
    const int warp_m = wid & 3;     // 0..3
    const int warp_n = wid >> 2;    // 0..1

    // Bias (+ w_a*alpha, inside tanh so NOT shift-invariant) and Vw to SMEM
    {
        float wa = __ldg(w_a) * ALPHA_S;
        int n = ntile * NTILE + (tid & 127);
        if (tid < 128) {
            smemf[BIAS_OFF + tid] = bw[n] + bz[n] + wa;
            smemf[VW_OFF + tid]   = Vw[n];
        }
    }

    wmma::fragment<wmma::accumulator, 16, 16, 8, float> acc[2][4];
#pragma unroll
    for (int i = 0; i < 2; i++)
#pragma unroll
        for (int j = 0; j < 4; j++)
            wmma::fill_fragment(acc[i][j], 0.0f);

    // Prologue: fill stages 0, 1
    fill_stage(smemf, smem_base, 0, 0, hidden, z, Ww, Wz, mtile, ntile, tid);
    fill_stage(smemf, smem_base, 1, 1, hidden, z, Ww, Wz, mtile, ntile, tid);

    for (int kc = 0; kc < NCHUNK; kc++) {
        // Fill stage kc+2 (its buffer was released by the barrier that ended iter kc-1)
        if (kc + 2 < NCHUNK) {
            fill_stage(smemf, smem_base, (kc + 2) % STAGES, kc + 2,
                       hidden, z, Ww, Wz, mtile, ntile, tid);
            CP_WAIT_GROUP(2);      // this thread's stage-kc data arrived
        } else if (kc + 2 == NCHUNK) {
            CP_WAIT_GROUP(1);
        } else {
            CP_WAIT_GROUP(0);
        }
        __syncthreads();           // everyone's stage-kc data visible

        const float* As = smemf + (kc % STAGES) * STAGE_FLOATS;
        const float* Bs = As + A_STAGE_FLOATS;

#pragma unroll
        for (int ks = 0; ks < KT / 8; ks++) {
            wmma::fragment<wmma::matrix_a, 16, 16, 8, wmma::precision::tf32, wmma::row_major> af[2];
            wmma::fragment<wmma::matrix_b, 16, 16, 8, wmma::precision::tf32, wmma::row_major> bf[4];
#pragma unroll
            for (int i = 0; i < 2; i++) {
                wmma::load_matrix_sync(af[i],
                    As + (warp_m * 32 + i * 16) * A_STRIDE + ks * 8, A_STRIDE);
#pragma unroll
                for (int t = 0; t < af[i].num_elements; t++)
                    af[i].x[t] = wmma::__float_to_tf32(af[i].x[t]);
            }
#pragma unroll
            for (int j = 0; j < 4; j++) {
                wmma::load_matrix_sync(bf[j],
                    Bs + (ks * 8) * B_STRIDE + warp_n * 64 + j * 16, B_STRIDE);
#pragma unroll
                for (int t = 0; t < bf[j].num_elements; t++)
                    bf[j].x[t] = wmma::__float_to_tf32(bf[j].x[t]);
            }
#pragma unroll
            for (int i = 0; i < 2; i++)
#pragma unroll
                for (int j = 0; j < 4; j++)
                    wmma::mma_sync(acc[i][j], af[i], bf[j], acc[i][j]);
        }
        __syncthreads();           // all reads of stage kc done before refill
    }

    // ---- Epilogue: C (128x128) -> SMEM (overlay stage area), tanh-dot ----
    float* Cs = smemf;             // 128 * 136 * 4 B = 69632 <= stage area
#pragma unroll
    for (int i = 0; i < 2; i++)
#pragma unroll
        for (int j = 0; j < 4; j++)
            wmma::store_matrix_sync(
                Cs + (warp_m * 32 + i * 16) * C_STRIDE + warp_n * 64 + j * 16,
                acc[i][j], C_STRIDE, wmma::mem_row_major);
    __syncthreads();

    // 256 threads: row = tid/2 (0..127), each thread sums 64 columns
    {
        int row  = tid >> 1;
        int half = tid & 1;
        const float* crow = Cs + row * C_STRIDE + half * 64;
        const float* bb   = smemf + BIAS_OFF + half * 64;
        const float* vv   = smemf + VW_OFF + half * 64;
        float acc_u = 0.0f;
#pragma unroll
        for (int c = 0; c < 64; c++) {
            float x = crow[c] + bb[c];
            float e = __expf(2.0f * x);
            float t = 1.0f - 2.0f / (e + 1.0f);   // tanh(x)
            acc_u += t * vv[c];
        }
        acc_u += __shfl_xor_sync(0xFFFFFFFFu, acc_u, 1);
        if (half == 0)
            g_part[(size_t)ntile * M_DIM + mtile * MT + row] = acc_u;
    }
}

// ----------------------------------------------------------------------------
// Kernel 2: softmax over sequence dim (one block per batch column)
// ----------------------------------------------------------------------------
__global__ void __launch_bounds__(256)
softmax_kernel(float* __restrict__ out) {
    int b = blockIdx.x;      // 0..15
    int tid = threadIdx.x;   // 0..255
    __shared__ float red[256];

    float u[8];
    float lmax = -1e30f;
#pragma unroll
    for (int i = 0; i < 8; i++) {
        int s = tid + i * 256;
        size_t m = (size_t)s * B_DIM + b;
        float v = 0.0f;
#pragma unroll
        for (int t = 0; t < NTILES; t++)
            v += g_part[(size_t)t * M_DIM + m];
        u[i] = v;
        lmax = fmaxf(lmax, v);
    }
    red[tid] = lmax;
    __syncthreads();
    for (int off = 128; off > 0; off >>= 1) {
        if (tid < off) red[tid] = fmaxf(red[tid], red[tid + off]);
        __syncthreads();
    }
    float gmax = red[0];
    __syncthreads();

    float lsum = 0.0f;
#pragma unroll
    for (int i = 0; i < 8; i++) {
        u[i] = __expf(u[i] - gmax);
        lsum += u[i];
    }
    red[tid] = lsum;
    __syncthreads();
    for (int off = 128; off > 0; off >>= 1) {
        if (tid < off) red[tid] += red[tid + off];
        __syncthreads();
    }
    float inv = 1.0f / red[0];
#pragma unroll
    for (int i = 0; i < 8; i++) {
        int s = tid + i * 256;
        out[(size_t)s * B_DIM + b] = u[i] * inv;
    }
}

// ----------------------------------------------------------------------------
// Launch
// ----------------------------------------------------------------------------
extern "C" void kernel_launch(void* const* d_in, const int* in_sizes, int n_in,
                              void* d_out, int out_size) {
    (void)in_sizes; (void)n_in; (void)out_size;
    const float* hidden = (const float*)d_in[0];
    const float* z      = (const float*)d_in[1];
    const float* Ww     = (const float*)d_in[2];
    const float* bw     = (const float*)d_in[3];
    const float* Wz     = (const float*)d_in[4];
    const float* bz     = (const float*)d_in[5];
    const float* Vw     = (const float*)d_in[6];
    // d_in[7] = vb (softmax-shift-invariant, unused)
    const float* w_a    = (const float*)d_in[8];
    float* out = (float*)d_out;

    static int smem_set = 0;
    if (!smem_set) {
        cudaFuncSetAttribute(dual_attn_gemm_kernel,
                             cudaFuncAttributeMaxDynamicSharedMemorySize, SMEM_BYTES);
        smem_set = 1;
    }

    dual_attn_gemm_kernel<<<dim3(NTILES, MTILES), 256, SMEM_BYTES>>>(
        hidden, z, Ww, Wz, bw, bz, Vw, w_a);
    softmax_kernel<<<B_DIM, 256>>>(out);
}

// round 11
// speedup vs baseline: 1.2252x; 1.2252x over previous
#include <cuda_runtime.h>
#include <cuda_bf16.h>
#include <mma.h>
#include <cstdint>
#include <math.h>

using namespace nvcuda;

// ----------------------------------------------------------------------------
// Problem constants
// ----------------------------------------------------------------------------
#define S_DIM   2048
#define B_DIM   16
#define H2_DIM  2048
#define V_DIM   1024
#define M_DIM   (S_DIM * B_DIM)          // 32768
#define K_TOT   (2 * H2_DIM)             // 4096
#define ALPHA_S 0.5f

// ----------------------------------------------------------------------------
// GEMM tiling: CTA 256x128, warp 64x64 (8 warps = 4x2), KT=32, 3 stages
// ----------------------------------------------------------------------------
#define MT 256
#define NTILE 128
#define KT 32
#define NCHUNK  (K_TOT / KT)             // 128
#define NTILES  (V_DIM / NTILE)          // 8
#define MTILES  (M_DIM / MT)             // 128
#define STAGES  3

// SMEM strides (floats), padded for bank-conflict relief
#define A_STRIDE 40                      // 32 + 8
#define B_STRIDE 136                     // 128 + 8
#define C_STRIDE 136

#define A_STAGE_FLOATS (MT * A_STRIDE)               // 10240
#define B_STAGE_FLOATS (KT * B_STRIDE)               // 4352
#define STAGE_FLOATS   (A_STAGE_FLOATS + B_STAGE_FLOATS)   // 14592
#define STAGE_AREA_FLOATS (STAGES * STAGE_FLOATS)    // 43776
#define BIAS_OFF  STAGE_AREA_FLOATS
#define VW_OFF    (BIAS_OFF + NTILE)
#define SMEM_FLOATS (VW_OFF + NTILE)                 // 44032
#define SMEM_BYTES (SMEM_FLOATS * 4)                 // 176128

// ----------------------------------------------------------------------------
// Device scratch (static — no runtime allocation)
// ----------------------------------------------------------------------------
__device__ __align__(128) float g_part[NTILES * M_DIM];   // 1 MB partial u

// ----------------------------------------------------------------------------
// cp.async helpers
// ----------------------------------------------------------------------------
__device__ __forceinline__ uint32_t smem_u32(const void* p) {
    uint32_t a;
    asm("{ .reg .u64 t; cvta.to.shared.u64 t, %1; cvt.u32.u64 %0, t; }" : "=r"(a) : "l"(p));
    return a;
}
__device__ __forceinline__ void cp_async16(uint32_t dst, const void* src) {
    asm volatile("cp.async.cg.shared.global [%0], [%1], 16;" :: "r"(dst), "l"(src) : "memory");
}
#define CP_COMMIT_GROUP()  asm volatile("cp.async.commit_group;" ::: "memory")
#define CP_WAIT_GROUP(n)   asm volatile("cp.async.wait_group %0;" :: "n"(n) : "memory")

// ----------------------------------------------------------------------------
// Stage fill: A tile [256 x 32] from hidden|z, B tile [32 x 128] from Ww|Wz
// 256 threads: 8 + 4 cp.async(16B) per thread.
// ----------------------------------------------------------------------------
__device__ __forceinline__ void fill_stage(
    uint32_t smem_base, int s, int kc,
    const float* __restrict__ hidden, const float* __restrict__ z,
    const float* __restrict__ Ww, const float* __restrict__ Wz,
    int mtile, int ntile, int tid)
{
    const int k0 = kc * KT;                     // global K offset (0..4095)
    uint32_t aBase = smem_base + (uint32_t)(s * STAGE_FLOATS) * 4u;
    uint32_t bBase = aBase + (uint32_t)A_STAGE_FLOATS * 4u;

    // A: 256 rows x 8 chunks(16B) = 2048 chunks
    {
        const float* abase = (k0 < H2_DIM) ? (hidden + k0) : (z + (k0 - H2_DIM));
#pragma unroll
        for (int i = 0; i < 8; i++) {
            int idx = tid + i * 256;
            int r = idx >> 3, g = idx & 7;
            const float* src = abase + (size_t)(mtile * MT + r) * H2_DIM + g * 4;
            uint32_t dst = aBase + (uint32_t)(r * A_STRIDE + g * 4) * 4u;
            cp_async16(dst, src);
        }
    }
    // B: 32 rows x 32 chunks(16B) = 1024 chunks
    {
        const float* bbase = (k0 < H2_DIM) ? (Ww + (size_t)k0 * V_DIM)
                                           : (Wz + (size_t)(k0 - H2_DIM) * V_DIM);
#pragma unroll
        for (int i = 0; i < 4; i++) {
            int idx = tid + i * 256;
            int r = idx >> 5, c = idx & 31;
            const float* src = bbase + (size_t)r * V_DIM + ntile * NTILE + c * 4;
            uint32_t dst = bBase + (uint32_t)(r * B_STRIDE + c * 4) * 4u;
            cp_async16(dst, src);
        }
    }
    CP_COMMIT_GROUP();
}

// ----------------------------------------------------------------------------
// Kernel 1: fused tf32 GEMM + tanh-dot epilogue -> g_part[ntile][m]
// ----------------------------------------------------------------------------
__global__ void __launch_bounds__(256, 1)
dual_attn_gemm_kernel(const float* __restrict__ hidden, const float* __restrict__ z,
                      const float* __restrict__ Ww,     const float* __restrict__ Wz,
                      const float* __restrict__ bw,     const float* __restrict__ bz,
                      const float* __restrict__ Vw,     const float* __restrict__ w_a)
{
    extern __shared__ float smemf[];
    uint32_t smem_base = smem_u32(smemf);
    const int tid = threadIdx.x;
    const int wid = tid >> 5;
    const int ntile = blockIdx.x;   // 0..7  (fastest -> B resident in L2 per wave)
    const int mtile = blockIdx.y;   // 0..127

    // Warp layout: 4 (M) x 2 (N); warp tile = 64 x 64
    const int warp_m = wid & 3;     // 0..3
    const int warp_n = wid >> 2;    // 0..1

    // Bias (+ w_a*alpha: inside tanh, NOT shift-invariant) and Vw to SMEM
    {
        float wa = __ldg(w_a) * ALPHA_S;
        if (tid < 128) {
            int n = ntile * NTILE + tid;
            smemf[BIAS_OFF + tid] = bw[n] + bz[n] + wa;
            smemf[VW_OFF + tid]   = Vw[n];
        }
    }

    wmma::fragment<wmma::accumulator, 16, 16, 8, float> acc[4][4];
#pragma unroll
    for (int i = 0; i < 4; i++)
#pragma unroll
        for (int j = 0; j < 4; j++)
            wmma::fill_fragment(acc[i][j], 0.0f);

    // Prologue: fill stages 0, 1
    fill_stage(smem_base, 0, 0, hidden, z, Ww, Wz, mtile, ntile, tid);
    fill_stage(smem_base, 1, 1, hidden, z, Ww, Wz, mtile, ntile, tid);

    for (int kc = 0; kc < NCHUNK; kc++) {
        if (kc + 2 < NCHUNK) {
            fill_stage(smem_base, (kc + 2) % STAGES, kc + 2,
                       hidden, z, Ww, Wz, mtile, ntile, tid);
            CP_WAIT_GROUP(2);      // stage-kc data (this thread) arrived
        } else if (kc + 2 == NCHUNK) {
            CP_WAIT_GROUP(1);
        } else {
            CP_WAIT_GROUP(0);
        }
        __syncthreads();           // stage-kc data visible to all

        const float* As = smemf + (kc % STAGES) * STAGE_FLOATS;
        const float* Bs = As + A_STAGE_FLOATS;

#pragma unroll
        for (int ks = 0; ks < KT / 8; ks++) {
            wmma::fragment<wmma::matrix_a, 16, 16, 8, wmma::precision::tf32, wmma::row_major> af[4];
            wmma::fragment<wmma::matrix_b, 16, 16, 8, wmma::precision::tf32, wmma::row_major> bf[4];
#pragma unroll
            for (int i = 0; i < 4; i++) {
                wmma::load_matrix_sync(af[i],
                    As + (warp_m * 64 + i * 16) * A_STRIDE + ks * 8, A_STRIDE);
#pragma unroll
                for (int t = 0; t < af[i].num_elements; t++)
                    af[i].x[t] = wmma::__float_to_tf32(af[i].x[t]);
            }
#pragma unroll
            for (int j = 0; j < 4; j++) {
                wmma::load_matrix_sync(bf[j],
                    Bs + (ks * 8) * B_STRIDE + warp_n * 64 + j * 16, B_STRIDE);
#pragma unroll
                for (int t = 0; t < bf[j].num_elements; t++)
                    bf[j].x[t] = wmma::__float_to_tf32(bf[j].x[t]);
            }
#pragma unroll
            for (int i = 0; i < 4; i++)
#pragma unroll
                for (int j = 0; j < 4; j++)
                    wmma::mma_sync(acc[i][j], af[i], bf[j], acc[i][j]);
        }
        __syncthreads();           // all reads of stage kc done before refill
    }

    // ---- Epilogue: C (256x128) -> SMEM overlay, tanh-dot with Vw ----
    float* Cs = smemf;             // 256 * 136 floats = 139264 B <= stage area
#pragma unroll
    for (int i = 0; i < 4; i++)
#pragma unroll
        for (int j = 0; j < 4; j++)
            wmma::store_matrix_sync(
                Cs + (warp_m * 64 + i * 16) * C_STRIDE + warp_n * 64 + j * 16,
                acc[i][j], C_STRIDE, wmma::mem_row_major);
    __syncthreads();

    // 256 threads: one row each, sum 128 columns
    {
        const float* crow = Cs + tid * C_STRIDE;
        const float* bb   = smemf + BIAS_OFF;
        const float* vv   = smemf + VW_OFF;
        float acc_u = 0.0f;
#pragma unroll 8
        for (int c = 0; c < NTILE; c++) {
            float x = crow[c] + bb[c];
            float e = __expf(2.0f * x);
            float t = 1.0f - 2.0f / (e + 1.0f);   // tanh(x)
            acc_u += t * vv[c];
        }
        g_part[(size_t)ntile * M_DIM + mtile * MT + tid] = acc_u;
    }
}

// ----------------------------------------------------------------------------
// Kernel 2: softmax over sequence dim (one block per batch column)
// ----------------------------------------------------------------------------
__global__ void __launch_bounds__(1024)
softmax_kernel(float* __restrict__ out) {
    int b = blockIdx.x;      // 0..15
    int tid = threadIdx.x;   // 0..1023
    __shared__ float red[1024];

    float u[2];
    float lmax = -1e30f;
#pragma unroll
    for (int i = 0; i < 2; i++) {
        int s = tid + i * 1024;
        size_t m = (size_t)s * B_DIM + b;
        float v = 0.0f;
#pragma unroll
        for (int t = 0; t < NTILES; t++)
            v += g_part[(size_t)t * M_DIM + m];
        u[i] = v;
        lmax = fmaxf(lmax, v);
    }
    red[tid] = lmax;
    __syncthreads();
    for (int off = 512; off > 0; off >>= 1) {
        if (tid < off) red[tid] = fmaxf(red[tid], red[tid + off]);
        __syncthreads();
    }
    float gmax = red[0];
    __syncthreads();

    float lsum = 0.0f;
#pragma unroll
    for (int i = 0; i < 2; i++) {
        u[i] = __expf(u[i] - gmax);
        lsum += u[i];
    }
    red[tid] = lsum;
    __syncthreads();
    for (int off = 512; off > 0; off >>= 1) {
        if (tid < off) red[tid] += red[tid + off];
        __syncthreads();
    }
    float inv = 1.0f / red[0];
#pragma unroll
    for (int i = 0; i < 2; i++) {
        int s = tid + i * 1024;
        out[(size_t)s * B_DIM + b] = u[i] * inv;
    }
}

// ----------------------------------------------------------------------------
// Launch
// ----------------------------------------------------------------------------
extern "C" void kernel_launch(void* const* d_in, const int* in_sizes, int n_in,
                              void* d_out, int out_size) {
    (void)in_sizes; (void)n_in; (void)out_size;
    const float* hidden = (const float*)d_in[0];
    const float* z      = (const float*)d_in[1];
    const float* Ww     = (const float*)d_in[2];
    const float* bw     = (const float*)d_in[3];
    const float* Wz     = (const float*)d_in[4];
    const float* bz     = (const float*)d_in[5];
    const float* Vw     = (const float*)d_in[6];
    // d_in[7] = vb (softmax-shift-invariant, unused)
    const float* w_a    = (const float*)d_in[8];
    float* out = (float*)d_out;

    static int smem_set = 0;
    if (!smem_set) {
        cudaFuncSetAttribute(dual_attn_gemm_kernel,
                             cudaFuncAttributeMaxDynamicSharedMemorySize, SMEM_BYTES);
        smem_set = 1;
    }

    dual_attn_gemm_kernel<<<dim3(NTILES, MTILES), 256, SMEM_BYTES>>>(
        hidden, z, Ww, Wz, bw, bz, Vw, w_a);
    softmax_kernel<<<B_DIM, 1024>>>(out);
}

// round 12
// speedup vs baseline: 2.3746x; 1.9381x over previous
#include <cuda_runtime.h>
#include <cuda_bf16.h>
#include <cstdint>
#include <math.h>

// ----------------------------------------------------------------------------
// Problem constants
// ----------------------------------------------------------------------------
#define S_DIM   2048
#define B_DIM   16
#define H2_DIM  2048
#define V_DIM   1024
#define M_DIM   (S_DIM * B_DIM)          // 32768
#define K_TOT   (2 * H2_DIM)             // 4096
#define ALPHA_S 0.5f

// ----------------------------------------------------------------------------
// GEMM tiling: CTA 256x128, warp 64x64 (8 warps = 4x2), KT=32, 3 stages
// ----------------------------------------------------------------------------
#define MT 256
#define NTILE 128
#define KT 32
#define NCHUNK  (K_TOT / KT)             // 128
#define NTILES  (V_DIM / NTILE)          // 8
#define MTILES  (M_DIM / MT)             // 128
#define STAGES  3

// SMEM strides (floats)
#define A_STRIDE 36    // 144 B rows: ldmatrix bank-groups 4r%32 -> conflict-free
#define B_STRIDE 136   // banks 8(t%4)+t/4 -> conflict-free B-fragment LDS
#define C_STRIDE 136

#define A_STAGE_FLOATS (MT * A_STRIDE)               // 9216
#define B_STAGE_FLOATS (KT * B_STRIDE)               // 4352
#define STAGE_FLOATS   (A_STAGE_FLOATS + B_STAGE_FLOATS)   // 13568
#define STAGE_BYTES    (STAGE_FLOATS * 4)            // 54272
#define STAGE_AREA_FLOATS (STAGES * STAGE_FLOATS)    // 40704
#define BIAS_OFF  STAGE_AREA_FLOATS
#define VW_OFF    (BIAS_OFF + NTILE)
#define SMEM_FLOATS (VW_OFF + NTILE)                 // 40960
#define SMEM_BYTES (SMEM_FLOATS * 4)                 // 163840

// ----------------------------------------------------------------------------
// Device scratch (static — no runtime allocation)
// ----------------------------------------------------------------------------
__device__ __align__(128) float g_A[(size_t)M_DIM * K_TOT];   // 512 MB  [m][k] = rn_tf32(hidden|z)
__device__ __align__(128) float g_B[(size_t)K_TOT * V_DIM];   // 16 MB   [k][n] = rn_tf32(Ww|Wz)
__device__ __align__(128) float g_part[NTILES * M_DIM];       // 1 MB

// ----------------------------------------------------------------------------
// PTX helpers
// ----------------------------------------------------------------------------
__device__ __forceinline__ uint32_t smem_u32(const void* p) {
    uint32_t a;
    asm("{ .reg .u64 t; cvta.to.shared.u64 t, %1; cvt.u32.u64 %0, t; }" : "=r"(a) : "l"(p));
    return a;
}
__device__ __forceinline__ void cp_async16(uint32_t dst, const void* src) {
    asm volatile("cp.async.cg.shared.global [%0], [%1], 16;" :: "r"(dst), "l"(src) : "memory");
}
#define CP_COMMIT_GROUP()  asm volatile("cp.async.commit_group;" ::: "memory")
#define CP_WAIT_GROUP(n)   asm volatile("cp.async.wait_group %0;" :: "n"(n) : "memory")

__device__ __forceinline__ void ldsm_x4(uint32_t* r, uint32_t addr) {
    asm volatile("ldmatrix.sync.aligned.m8n8.x4.shared.b16 {%0,%1,%2,%3}, [%4];"
                 : "=r"(r[0]), "=r"(r[1]), "=r"(r[2]), "=r"(r[3]) : "r"(addr));
}
__device__ __forceinline__ void mma_tf32(float* c, const uint32_t* a, const uint32_t* b) {
    asm volatile(
        "mma.sync.aligned.m16n8k8.row.col.f32.tf32.tf32.f32 "
        "{%0,%1,%2,%3}, {%4,%5,%6,%7}, {%8,%9}, {%0,%1,%2,%3};"
        : "+f"(c[0]), "+f"(c[1]), "+f"(c[2]), "+f"(c[3])
        : "r"(a[0]), "r"(a[1]), "r"(a[2]), "r"(a[3]), "r"(b[0]), "r"(b[1]));
}
__device__ __forceinline__ float rn_tf32(float x) {
    uint32_t r;
    asm("cvt.rna.tf32.f32 %0, %1;" : "=r"(r) : "f"(x));
    return __uint_as_float(r);
}

// ----------------------------------------------------------------------------
// Kernel 0a: pre-round A = [hidden | z] -> g_A[m][4096], RN to tf32
// ----------------------------------------------------------------------------
__global__ void __launch_bounds__(256)
preround_A(const float4* __restrict__ hidden, const float4* __restrict__ z) {
    size_t idx = (size_t)blockIdx.x * 256 + threadIdx.x;   // over M*1024 float4
    size_t m = idx >> 10;
    int kk = (int)(idx & 1023);
    float4 v = (kk < 512) ? hidden[m * 512 + kk] : z[m * 512 + (kk - 512)];
    v.x = rn_tf32(v.x); v.y = rn_tf32(v.y); v.z = rn_tf32(v.z); v.w = rn_tf32(v.w);
    reinterpret_cast<float4*>(g_A)[idx] = v;
}

// ----------------------------------------------------------------------------
// Kernel 0b: pre-round B = [Ww ; Wz] -> g_B[k][1024], RN to tf32
// ----------------------------------------------------------------------------
__global__ void __launch_bounds__(256)
preround_B(const float4* __restrict__ Ww, const float4* __restrict__ Wz) {
    size_t idx = (size_t)blockIdx.x * 256 + threadIdx.x;   // over 4096*256 float4
    size_t k = idx >> 8;
    int c = (int)(idx & 255);
    float4 v = (k < H2_DIM) ? Ww[k * 256 + c] : Wz[(k - H2_DIM) * 256 + c];
    v.x = rn_tf32(v.x); v.y = rn_tf32(v.y); v.z = rn_tf32(v.z); v.w = rn_tf32(v.w);
    reinterpret_cast<float4*>(g_B)[idx] = v;
}

// ----------------------------------------------------------------------------
// Stage fill: A tile [256 x 32], B tile [32 x 128]; 256 threads, 8+4 cp.async
// ----------------------------------------------------------------------------
__device__ __forceinline__ void fill_stage(
    uint32_t smem_base, int s, int kc, int mtile, int ntile, int tid)
{
    const int k0 = kc * KT;
    uint32_t aBase = smem_base + (uint32_t)(s * STAGE_BYTES);
    uint32_t bBase = aBase + (uint32_t)(A_STAGE_FLOATS * 4);

    // A: 256 rows x 8 chunks(16B)
    const float* abase = g_A + k0;
#pragma unroll
    for (int i = 0; i < 8; i++) {
        int idx = tid + i * 256;
        int r = idx >> 3, g = idx & 7;
        const float* src = abase + (size_t)(mtile * MT + r) * K_TOT + g * 4;
        uint32_t dst = aBase + (uint32_t)(r * A_STRIDE + g * 4) * 4u;
        cp_async16(dst, src);
    }
    // B: 32 rows x 32 chunks(16B)
    const float* bbase = g_B + (size_t)k0 * V_DIM + ntile * NTILE;
#pragma unroll
    for (int i = 0; i < 4; i++) {
        int idx = tid + i * 256;
        int r = idx >> 5, c = idx & 31;
        const float* src = bbase + (size_t)r * V_DIM + c * 4;
        uint32_t dst = bBase + (uint32_t)(r * B_STRIDE + c * 4) * 4u;
        cp_async16(dst, src);
    }
    CP_COMMIT_GROUP();
}

// ----------------------------------------------------------------------------
// Kernel 1: fused tf32 GEMM (raw mma.sync + ldmatrix) + tanh-dot epilogue
// ----------------------------------------------------------------------------
__global__ void __launch_bounds__(256, 1)
dual_attn_gemm_kernel(const float* __restrict__ bw, const float* __restrict__ bz,
                      const float* __restrict__ Vw, const float* __restrict__ w_a)
{
    extern __shared__ float smemf[];
    uint32_t smem_base = smem_u32(smemf);
    const int tid  = threadIdx.x;
    const int wid  = tid >> 5;
    const int lane = tid & 31;
    const int ntile = blockIdx.x;   // 0..7 (fastest -> B resident in L2 per wave)
    const int mtile = blockIdx.y;   // 0..127

    const int warp_m = wid & 3;     // 0..3  (64-row slab)
    const int warp_n = wid >> 2;    // 0..1  (64-col slab)

    // ldmatrix lane mapping: q = lane/8 selects quadrant
    //   q0: rows 0-7 cols 0-3 | q1: rows 8-15 cols 0-3 | q2: rows 0-7 cols 4-7 | q3: rows 8-15 cols 4-7
    const int q = lane >> 3;
    const int a_row = (q & 1) * 8 + (lane & 7);
    const uint32_t aLaneOff = (uint32_t)(((warp_m * 64 + a_row) * A_STRIDE + (q >> 1) * 4) * 4);

    // Bias (+ w_a*alpha: inside tanh, NOT shift-invariant) and Vw
    {
        float wa = __ldg(w_a) * ALPHA_S;
        if (tid < 128) {
            int n = ntile * NTILE + tid;
            smemf[BIAS_OFF + tid] = bw[n] + bz[n] + wa;
            smemf[VW_OFF + tid]   = Vw[n];
        }
    }

    float acc[4][8][4];
#pragma unroll
    for (int i = 0; i < 4; i++)
#pragma unroll
        for (int j = 0; j < 8; j++)
#pragma unroll
            for (int t = 0; t < 4; t++)
                acc[i][j][t] = 0.0f;

    fill_stage(smem_base, 0, 0, mtile, ntile, tid);
    fill_stage(smem_base, 1, 1, mtile, ntile, tid);

    for (int kc = 0; kc < NCHUNK; kc++) {
        if (kc + 2 < NCHUNK) {
            fill_stage(smem_base, (kc + 2) % STAGES, kc + 2, mtile, ntile, tid);
            CP_WAIT_GROUP(2);
        } else if (kc + 2 == NCHUNK) {
            CP_WAIT_GROUP(1);
        } else {
            CP_WAIT_GROUP(0);
        }
        __syncthreads();

        const int s = kc % STAGES;
        const uint32_t aStage = smem_base + (uint32_t)(s * STAGE_BYTES);
        const float* Bs = smemf + s * STAGE_FLOATS + A_STAGE_FLOATS;
        const float* bptr0 = Bs + (lane & 3) * B_STRIDE + warp_n * 64 + (lane >> 2);

#pragma unroll
        for (int ks = 0; ks < KT / 8; ks++) {
            uint32_t a[4][4];
#pragma unroll
            for (int i = 0; i < 4; i++)
                ldsm_x4(a[i], aStage + aLaneOff + (uint32_t)(i * 16 * A_STRIDE * 4 + ks * 32));

            uint32_t b[8][2];
            const float* bp = bptr0 + ks * 8 * B_STRIDE;
#pragma unroll
            for (int j = 0; j < 8; j++) {
                b[j][0] = __float_as_uint(bp[j * 8]);
                b[j][1] = __float_as_uint(bp[4 * B_STRIDE + j * 8]);
            }
#pragma unroll
            for (int i = 0; i < 4; i++)
#pragma unroll
                for (int j = 0; j < 8; j++)
                    mma_tf32(acc[i][j], a[i], b[j]);
        }
        __syncthreads();
    }

    // ---- Epilogue: acc -> SMEM overlay (256 x 136), tanh-dot with Vw ----
    float* Cs = smemf;   // 256*136 floats = 139264 B <= stage area
    {
        int gr = lane >> 2, gc = lane & 3;
#pragma unroll
        for (int i = 0; i < 4; i++) {
            int r0 = warp_m * 64 + i * 16 + gr;
#pragma unroll
            for (int j = 0; j < 8; j++) {
                int c0 = warp_n * 64 + j * 8 + 2 * gc;
                *reinterpret_cast<float2*>(Cs + r0 * C_STRIDE + c0) =
                    make_float2(acc[i][j][0], acc[i][j][1]);
                *reinterpret_cast<float2*>(Cs + (r0 + 8) * C_STRIDE + c0) =
                    make_float2(acc[i][j][2], acc[i][j][3]);
            }
        }
    }
    __syncthreads();

    // 256 threads: one row each, sum 128 columns
    {
        const float* crow = Cs + tid * C_STRIDE;
        const float* bb   = smemf + BIAS_OFF;
        const float* vv   = smemf + VW_OFF;
        float acc_u = 0.0f;
#pragma unroll 8
        for (int c = 0; c < NTILE; c++) {
            float x = crow[c] + bb[c];
            float e = __expf(2.0f * x);
            float t = 1.0f - 2.0f / (e + 1.0f);   // tanh(x)
            acc_u += t * vv[c];
        }
        g_part[(size_t)ntile * M_DIM + mtile * MT + tid] = acc_u;
    }
}

// ----------------------------------------------------------------------------
// Kernel 2: softmax over sequence dim (one block per batch column)
// ----------------------------------------------------------------------------
__global__ void __launch_bounds__(1024)
softmax_kernel(float* __restrict__ out) {
    int b = blockIdx.x;      // 0..15
    int tid = threadIdx.x;   // 0..1023
    __shared__ float red[1024];

    float u[2];
    float lmax = -1e30f;
#pragma unroll
    for (int i = 0; i < 2; i++) {
        int s = tid + i * 1024;
        size_t m = (size_t)s * B_DIM + b;
        float v = 0.0f;
#pragma unroll
        for (int t = 0; t < NTILES; t++)
            v += g_part[(size_t)t * M_DIM + m];
        u[i] = v;
        lmax = fmaxf(lmax, v);
    }
    red[tid] = lmax;
    __syncthreads();
    for (int off = 512; off > 0; off >>= 1) {
        if (tid < off) red[tid] = fmaxf(red[tid], red[tid + off]);
        __syncthreads();
    }
    float gmax = red[0];
    __syncthreads();

    float lsum = 0.0f;
#pragma unroll
    for (int i = 0; i < 2; i++) {
        u[i] = __expf(u[i] - gmax);
        lsum += u[i];
    }
    red[tid] = lsum;
    __syncthreads();
    for (int off = 512; off > 0; off >>= 1) {
        if (tid < off) red[tid] += red[tid + off];
        __syncthreads();
    }
    float inv = 1.0f / red[0];
#pragma unroll
    for (int i = 0; i < 2; i++) {
        int s = tid + i * 1024;
        out[(size_t)s * B_DIM + b] = u[i] * inv;
    }
}

// ----------------------------------------------------------------------------
// Launch
// ----------------------------------------------------------------------------
extern "C" void kernel_launch(void* const* d_in, const int* in_sizes, int n_in,
                              void* d_out, int out_size) {
    (void)in_sizes; (void)n_in; (void)out_size;
    const float* hidden = (const float*)d_in[0];
    const float* z      = (const float*)d_in[1];
    const float* Ww     = (const float*)d_in[2];
    const float* bw     = (const float*)d_in[3];
    const float* Wz     = (const float*)d_in[4];
    const float* bz     = (const float*)d_in[5];
    const float* Vw     = (const float*)d_in[6];
    // d_in[7] = vb (softmax-shift-invariant, unused)
    const float* w_a    = (const float*)d_in[8];
    float* out = (float*)d_out;

    static int smem_set = 0;
    if (!smem_set) {
        cudaFuncSetAttribute(dual_attn_gemm_kernel,
                             cudaFuncAttributeMaxDynamicSharedMemorySize, SMEM_BYTES);
        smem_set = 1;
    }

    // Pre-round inputs to tf32 (RN) into fused scratch layouts
    preround_A<<<(int)(((size_t)M_DIM * 1024) / 256), 256>>>(
        (const float4*)hidden, (const float4*)z);
    preround_B<<<(int)(((size_t)K_TOT * 256) / 256), 256>>>(
        (const float4*)Ww, (const float4*)Wz);

    dual_attn_gemm_kernel<<<dim3(NTILES, MTILES), 256, SMEM_BYTES>>>(bw, bz, Vw, w_a);
    softmax_kernel<<<B_DIM, 1024>>>(out);
}

// round 13
// speedup vs baseline: 2.4889x; 1.0481x over previous
#include <cuda_runtime.h>
#include <cuda_bf16.h>
#include <cstdint>
#include <math.h>

// ----------------------------------------------------------------------------
// Problem constants
// ----------------------------------------------------------------------------
#define S_DIM   2048
#define B_DIM   16
#define H2_DIM  2048
#define V_DIM   1024
#define M_DIM   (S_DIM * B_DIM)          // 32768
#define K_TOT   (2 * H2_DIM)             // 4096
#define ALPHA_S 0.5f

// ----------------------------------------------------------------------------
// GEMM tiling: CTA 256x128, warp 64x64 (8 warps = 4x2), KT=64, 2 stages
// ----------------------------------------------------------------------------
#define MT 256
#define NTILE 128
#define KT 64
#define NCHUNK  (K_TOT / KT)             // 64
#define NTILES  (V_DIM / NTILE)          // 8
#define MTILES  (M_DIM / MT)             // 128
#define STAGES  2

// SMEM strides (floats)
#define A_STRIDE 68    // 68%32=4 -> ldmatrix banks 4r: conflict-free
#define B_STRIDE 136   // banks 8(lane%4)+lane/4: conflict-free
#define C_STRIDE 136

#define A_STAGE_FLOATS (MT * A_STRIDE)               // 17408
#define B_STAGE_FLOATS (KT * B_STRIDE)               // 8704
#define STAGE_FLOATS   (A_STAGE_FLOATS + B_STAGE_FLOATS)   // 26112
#define STAGE_BYTES    (STAGE_FLOATS * 4)            // 104448
#define STAGE_AREA_FLOATS (STAGES * STAGE_FLOATS)    // 52224
#define BIAS_OFF  STAGE_AREA_FLOATS
#define VW_OFF    (BIAS_OFF + NTILE)
#define SMEM_FLOATS (VW_OFF + NTILE)                 // 52480
#define SMEM_BYTES (SMEM_FLOATS * 4)                 // 209920

// ----------------------------------------------------------------------------
// Device scratch (static — no runtime allocation)
// ----------------------------------------------------------------------------
__device__ __align__(128) float g_A[(size_t)M_DIM * K_TOT];   // 512 MB [m][k] = rn_tf32(hidden|z)
__device__ __align__(128) float g_B[(size_t)K_TOT * V_DIM];   // 16 MB  [k][n] = rn_tf32(Ww|Wz)
__device__ __align__(128) float g_part[NTILES * M_DIM];       // 1 MB

// ----------------------------------------------------------------------------
// PTX helpers
// ----------------------------------------------------------------------------
__device__ __forceinline__ uint32_t smem_u32(const void* p) {
    uint32_t a;
    asm("{ .reg .u64 t; cvta.to.shared.u64 t, %1; cvt.u32.u64 %0, t; }" : "=r"(a) : "l"(p));
    return a;
}
__device__ __forceinline__ void cp_async16(uint32_t dst, const void* src) {
    asm volatile("cp.async.cg.shared.global [%0], [%1], 16;" :: "r"(dst), "l"(src) : "memory");
}
#define CP_COMMIT_GROUP()  asm volatile("cp.async.commit_group;" ::: "memory")
#define CP_WAIT_GROUP(n)   asm volatile("cp.async.wait_group %0;" :: "n"(n) : "memory")

__device__ __forceinline__ void ldsm_x4(uint32_t* r, uint32_t addr) {
    asm volatile("ldmatrix.sync.aligned.m8n8.x4.shared.b16 {%0,%1,%2,%3}, [%4];"
                 : "=r"(r[0]), "=r"(r[1]), "=r"(r[2]), "=r"(r[3]) : "r"(addr));
}
__device__ __forceinline__ void mma_tf32(float* c, const uint32_t* a, const uint32_t* b) {
    asm volatile(
        "mma.sync.aligned.m16n8k8.row.col.f32.tf32.tf32.f32 "
        "{%0,%1,%2,%3}, {%4,%5,%6,%7}, {%8,%9}, {%0,%1,%2,%3};"
        : "+f"(c[0]), "+f"(c[1]), "+f"(c[2]), "+f"(c[3])
        : "r"(a[0]), "r"(a[1]), "r"(a[2]), "r"(a[3]), "r"(b[0]), "r"(b[1]));
}
__device__ __forceinline__ float rn_tf32(float x) {
    uint32_t r;
    asm("cvt.rna.tf32.f32 %0, %1;" : "=r"(r) : "f"(x));
    return __uint_as_float(r);
}

// ----------------------------------------------------------------------------
// Kernel 0a: pre-round A = [hidden | z] -> g_A[m][4096], RN to tf32
// ----------------------------------------------------------------------------
__global__ void __launch_bounds__(256)
preround_A(const float4* __restrict__ hidden, const float4* __restrict__ z) {
    size_t idx = (size_t)blockIdx.x * 256 + threadIdx.x;   // over M*1024 float4
    size_t m = idx >> 10;
    int kk = (int)(idx & 1023);
    float4 v = (kk < 512) ? hidden[m * 512 + kk] : z[m * 512 + (kk - 512)];
    v.x = rn_tf32(v.x); v.y = rn_tf32(v.y); v.z = rn_tf32(v.z); v.w = rn_tf32(v.w);
    reinterpret_cast<float4*>(g_A)[idx] = v;
}

// ----------------------------------------------------------------------------
// Kernel 0b: pre-round B = [Ww ; Wz] -> g_B[k][1024], RN to tf32
// ----------------------------------------------------------------------------
__global__ void __launch_bounds__(256)
preround_B(const float4* __restrict__ Ww, const float4* __restrict__ Wz) {
    size_t idx = (size_t)blockIdx.x * 256 + threadIdx.x;   // over 4096*256 float4
    size_t k = idx >> 8;
    int c = (int)(idx & 255);
    float4 v = (k < H2_DIM) ? Ww[k * 256 + c] : Wz[(k - H2_DIM) * 256 + c];
    v.x = rn_tf32(v.x); v.y = rn_tf32(v.y); v.z = rn_tf32(v.z); v.w = rn_tf32(v.w);
    reinterpret_cast<float4*>(g_B)[idx] = v;
}

// ----------------------------------------------------------------------------
// Stage fill: A tile [256 x 64], B tile [64 x 128]; 256 threads, 16+8 cp.async
// ----------------------------------------------------------------------------
__device__ __forceinline__ void fill_stage(
    uint32_t smem_base, int slot, int kc, int mtile, int ntile, int tid)
{
    const int k0 = kc * KT;
    uint32_t aBase = smem_base + (uint32_t)(slot * STAGE_BYTES);
    uint32_t bBase = aBase + (uint32_t)(A_STAGE_FLOATS * 4);

    // A: 256 rows x 16 chunks(16B) = 4096 chunks
    const float* abase = g_A + k0;
#pragma unroll
    for (int i = 0; i < 16; i++) {
        int idx = tid + i * 256;
        int r = idx >> 4, g = idx & 15;
        const float* src = abase + (size_t)(mtile * MT + r) * K_TOT + g * 4;
        uint32_t dst = aBase + (uint32_t)(r * A_STRIDE + g * 4) * 4u;
        cp_async16(dst, src);
    }
    // B: 64 rows x 32 chunks(16B) = 2048 chunks
    const float* bbase = g_B + (size_t)k0 * V_DIM + ntile * NTILE;
#pragma unroll
    for (int i = 0; i < 8; i++) {
        int idx = tid + i * 256;
        int r = idx >> 5, c = idx & 31;
        const float* src = bbase + (size_t)r * V_DIM + c * 4;
        uint32_t dst = bBase + (uint32_t)(r * B_STRIDE + c * 4) * 4u;
        cp_async16(dst, src);
    }
    CP_COMMIT_GROUP();
}

// ----------------------------------------------------------------------------
// Kernel 1: fused tf32 GEMM (mma.sync + ldmatrix, fragment double-buffering)
// ----------------------------------------------------------------------------
__global__ void __launch_bounds__(256, 1)
dual_attn_gemm_kernel(const float* __restrict__ bw, const float* __restrict__ bz,
                      const float* __restrict__ Vw, const float* __restrict__ w_a)
{
    extern __shared__ float smemf[];
    uint32_t smem_base = smem_u32(smemf);
    const int tid  = threadIdx.x;
    const int wid  = tid >> 5;
    const int lane = tid & 31;
    const int ntile = blockIdx.x;   // 0..7 (fastest -> B resident in L2 per wave)
    const int mtile = blockIdx.y;   // 0..127

    const int warp_m = wid & 3;     // 64-row slab
    const int warp_n = wid >> 2;    // 64-col slab

    // ldmatrix quadrant mapping
    const int q = lane >> 3;
    const int a_row = (q & 1) * 8 + (lane & 7);
    const uint32_t aLaneOff = (uint32_t)(((warp_m * 64 + a_row) * A_STRIDE + (q >> 1) * 4) * 4);
    const int bColOff = warp_n * 64 + (lane >> 2);
    const int bRowOff = (lane & 3) * B_STRIDE;

    // Bias (+ w_a*alpha: inside tanh, NOT shift-invariant) and Vw
    {
        float wa = __ldg(w_a) * ALPHA_S;
        if (tid < 128) {
            int n = ntile * NTILE + tid;
            smemf[BIAS_OFF + tid] = bw[n] + bz[n] + wa;
            smemf[VW_OFF + tid]   = Vw[n];
        }
    }

    float acc[4][8][4];
#pragma unroll
    for (int i = 0; i < 4; i++)
#pragma unroll
        for (int j = 0; j < 8; j++)
#pragma unroll
            for (int t = 0; t < 4; t++)
                acc[i][j][t] = 0.0f;

    fill_stage(smem_base, 0, 0, mtile, ntile, tid);
    fill_stage(smem_base, 1, 1, mtile, ntile, tid);

    for (int kc = 0; kc < NCHUNK; kc++) {
        if (kc < NCHUNK - 1) { CP_WAIT_GROUP(1); } else { CP_WAIT_GROUP(0); }
        __syncthreads();

        const int slot = kc & 1;
        const uint32_t aStage = smem_base + (uint32_t)(slot * STAGE_BYTES);
        const float* Bs = smemf + slot * STAGE_FLOATS + A_STAGE_FLOATS;
        const float* bptr0 = Bs + bRowOff + bColOff;

        uint32_t a[2][4][4];
        uint32_t b[2][8][2];

        // preload ks=0 fragments
#pragma unroll
        for (int i = 0; i < 4; i++)
            ldsm_x4(a[0][i], aStage + aLaneOff + (uint32_t)(i * 16 * A_STRIDE * 4));
#pragma unroll
        for (int j = 0; j < 8; j++) {
            b[0][j][0] = __float_as_uint(bptr0[j * 8]);
            b[0][j][1] = __float_as_uint(bptr0[4 * B_STRIDE + j * 8]);
        }

#pragma unroll
        for (int ks = 0; ks < KT / 8; ks++) {
            const int cur = ks & 1;
            const int nxt = cur ^ 1;
            if (ks < KT / 8 - 1) {
                // prefetch ks+1 fragments; latency hides under the 32 MMAs below
#pragma unroll
                for (int i = 0; i < 4; i++)
                    ldsm_x4(a[nxt][i],
                            aStage + aLaneOff +
                            (uint32_t)(i * 16 * A_STRIDE * 4 + (ks + 1) * 32));
                const float* bp = bptr0 + (ks + 1) * 8 * B_STRIDE;
#pragma unroll
                for (int j = 0; j < 8; j++) {
                    b[nxt][j][0] = __float_as_uint(bp[j * 8]);
                    b[nxt][j][1] = __float_as_uint(bp[4 * B_STRIDE + j * 8]);
                }
            }
#pragma unroll
            for (int i = 0; i < 4; i++)
#pragma unroll
                for (int j = 0; j < 8; j++)
                    mma_tf32(acc[i][j], a[cur][i], b[cur][j]);
        }
        __syncthreads();

        if (kc + 2 < NCHUNK)
            fill_stage(smem_base, slot, kc + 2, mtile, ntile, tid);
    }

    // ---- Epilogue: acc -> SMEM overlay (256 x 136), tanh-dot with Vw ----
    float* Cs = smemf;   // 256*136*4 = 139264 B <= stage area
    {
        int gr = lane >> 2, gc = lane & 3;
#pragma unroll
        for (int i = 0; i < 4; i++) {
            int r0 = warp_m * 64 + i * 16 + gr;
#pragma unroll
            for (int j = 0; j < 8; j++) {
                int c0 = warp_n * 64 + j * 8 + 2 * gc;
                *reinterpret_cast<float2*>(Cs + r0 * C_STRIDE + c0) =
                    make_float2(acc[i][j][0], acc[i][j][1]);
                *reinterpret_cast<float2*>(Cs + (r0 + 8) * C_STRIDE + c0) =
                    make_float2(acc[i][j][2], acc[i][j][3]);
            }
        }
    }
    __syncthreads();

    // 256 threads: one row each, sum 128 columns
    {
        const float* crow = Cs + tid * C_STRIDE;
        const float* bb   = smemf + BIAS_OFF;
        const float* vv   = smemf + VW_OFF;
        float acc_u = 0.0f;
#pragma unroll 8
        for (int c = 0; c < NTILE; c++) {
            float x = crow[c] + bb[c];
            float e = __expf(2.0f * x);
            float t = 1.0f - 2.0f / (e + 1.0f);   // tanh(x)
            acc_u += t * vv[c];
        }
        g_part[(size_t)ntile * M_DIM + mtile * MT + tid] = acc_u;
    }
}

// ----------------------------------------------------------------------------
// Kernel 2: softmax over sequence dim (one block per batch column)
// ----------------------------------------------------------------------------
__global__ void __launch_bounds__(1024)
softmax_kernel(float* __restrict__ out) {
    int b = blockIdx.x;      // 0..15
    int tid = threadIdx.x;   // 0..1023
    __shared__ float red[1024];

    float u[2];
    float lmax = -1e30f;
#pragma unroll
    for (int i = 0; i < 2; i++) {
        int s = tid + i * 1024;
        size_t m = (size_t)s * B_DIM + b;
        float v = 0.0f;
#pragma unroll
        for (int t = 0; t < NTILES; t++)
            v += g_part[(size_t)t * M_DIM + m];
        u[i] = v;
        lmax = fmaxf(lmax, v);
    }
    red[tid] = lmax;
    __syncthreads();
    for (int off = 512; off > 0; off >>= 1) {
        if (tid < off) red[tid] = fmaxf(red[tid], red[tid + off]);
        __syncthreads();
    }
    float gmax = red[0];
    __syncthreads();

    float lsum = 0.0f;
#pragma unroll
    for (int i = 0; i < 2; i++) {
        u[i] = __expf(u[i] - gmax);
        lsum += u[i];
    }
    red[tid] = lsum;
    __syncthreads();
    for (int off = 512; off > 0; off >>= 1) {
        if (tid < off) red[tid] += red[tid + off];
        __syncthreads();
    }
    float inv = 1.0f / red[0];
#pragma unroll
    for (int i = 0; i < 2; i++) {
        int s = tid + i * 1024;
        out[(size_t)s * B_DIM + b] = u[i] * inv;
    }
}

// ----------------------------------------------------------------------------
// Launch
// ----------------------------------------------------------------------------
extern "C" void kernel_launch(void* const* d_in, const int* in_sizes, int n_in,
                              void* d_out, int out_size) {
    (void)in_sizes; (void)n_in; (void)out_size;
    const float* hidden = (const float*)d_in[0];
    const float* z      = (const float*)d_in[1];
    const float* Ww     = (const float*)d_in[2];
    const float* bw     = (const float*)d_in[3];
    const float* Wz     = (const float*)d_in[4];
    const float* bz     = (const float*)d_in[5];
    const float* Vw     = (const float*)d_in[6];
    // d_in[7] = vb (softmax-shift-invariant, unused)
    const float* w_a    = (const float*)d_in[8];
    float* out = (float*)d_out;

    static int smem_set = 0;
    if (!smem_set) {
        cudaFuncSetAttribute(dual_attn_gemm_kernel,
                             cudaFuncAttributeMaxDynamicSharedMemorySize, SMEM_BYTES);
        smem_set = 1;
    }

    preround_A<<<(int)(((size_t)M_DIM * 1024) / 256), 256>>>(
        (const float4*)hidden, (const float4*)z);
    preround_B<<<(int)(((size_t)K_TOT * 256) / 256), 256>>>(
        (const float4*)Ww, (const float4*)Wz);

    dual_attn_gemm_kernel<<<dim3(NTILES, MTILES), 256, SMEM_BYTES>>>(bw, bz, Vw, w_a);
    softmax_kernel<<<B_DIM, 1024>>>(out);
}

// round 14
// speedup vs baseline: 4.3187x; 1.7352x over previous
#include <cuda_runtime.h>
#include <cuda_fp16.h>
#include <cstdint>
#include <math.h>

// ----------------------------------------------------------------------------
// Problem constants
// ----------------------------------------------------------------------------
#define S_DIM   2048
#define B_DIM   16
#define H2_DIM  2048
#define V_DIM   1024
#define M_DIM   (S_DIM * B_DIM)          // 32768
#define K_TOT   (2 * H2_DIM)             // 4096
#define ALPHA_S 0.5f

// ----------------------------------------------------------------------------
// GEMM tiling: CTA 256x128, warp 64x64 (8 warps = 4x2), KT=64, 3 stages, fp16
// ----------------------------------------------------------------------------
#define MT 256
#define NTILE 128
#define KT 64
#define NCHUNK  (K_TOT / KT)             // 64
#define NTILES  (V_DIM / NTILE)          // 8
#define MTILES  (M_DIM / MT)             // 128
#define STAGES  3

// SMEM strides in HALVES. Byte row strides ≡ 16 (mod 128) -> every ldmatrix
// quadrant hits 8 distinct 16B bank groups: conflict-free.
#define A_STRIDE_H 72    // 144 B rows
#define B_STRIDE_H 136   // 272 B rows
#define C_STRIDE   136   // floats (epilogue overlay)

#define A_STAGE_HALVES (MT * A_STRIDE_H)             // 18432
#define B_STAGE_HALVES (KT * B_STRIDE_H)             // 8704
#define STAGE_HALVES   (A_STAGE_HALVES + B_STAGE_HALVES)   // 27136
#define STAGE_BYTES    (STAGE_HALVES * 2)            // 54272
#define STAGE_AREA_BYTES (STAGES * STAGE_BYTES)      // 162816
#define BIAS_OFF_B  STAGE_AREA_BYTES                 // bytes
#define VW_OFF_B    (BIAS_OFF_B + NTILE * 4)
#define SMEM_BYTES  (VW_OFF_B + NTILE * 4)           // 163840

// ----------------------------------------------------------------------------
// Device scratch (static — no runtime allocation)
// ----------------------------------------------------------------------------
__device__ __align__(128) __half g_A[(size_t)M_DIM * K_TOT];   // 256 MB [m][k] = rn_fp16(hidden|z)
__device__ __align__(128) __half g_B[(size_t)K_TOT * V_DIM];   // 8 MB   [k][n] = rn_fp16(Ww|Wz)
__device__ __align__(128) float  g_part[NTILES * M_DIM];       // 1 MB

// ----------------------------------------------------------------------------
// PTX helpers
// ----------------------------------------------------------------------------
__device__ __forceinline__ uint32_t smem_u32(const void* p) {
    uint32_t a;
    asm("{ .reg .u64 t; cvta.to.shared.u64 t, %1; cvt.u32.u64 %0, t; }" : "=r"(a) : "l"(p));
    return a;
}
__device__ __forceinline__ void cp_async16(uint32_t dst, const void* src) {
    asm volatile("cp.async.cg.shared.global [%0], [%1], 16;" :: "r"(dst), "l"(src) : "memory");
}
#define CP_COMMIT_GROUP()  asm volatile("cp.async.commit_group;" ::: "memory")
#define CP_WAIT_GROUP(n)   asm volatile("cp.async.wait_group %0;" :: "n"(n) : "memory")

__device__ __forceinline__ void ldsm_x4(uint32_t* r, uint32_t addr) {
    asm volatile("ldmatrix.sync.aligned.m8n8.x4.shared.b16 {%0,%1,%2,%3}, [%4];"
                 : "=r"(r[0]), "=r"(r[1]), "=r"(r[2]), "=r"(r[3]) : "r"(addr));
}
__device__ __forceinline__ void ldsm_x4_trans(uint32_t& r0, uint32_t& r1,
                                              uint32_t& r2, uint32_t& r3, uint32_t addr) {
    asm volatile("ldmatrix.sync.aligned.m8n8.x4.trans.shared.b16 {%0,%1,%2,%3}, [%4];"
                 : "=r"(r0), "=r"(r1), "=r"(r2), "=r"(r3) : "r"(addr));
}
// fp16 MMA, fp32 accumulate: D = A(16x16) * B(16x8) + D
__device__ __forceinline__ void mma_f16(float* c, const uint32_t* a, const uint32_t* b) {
    asm volatile(
        "mma.sync.aligned.m16n8k16.row.col.f32.f16.f16.f32 "
        "{%0,%1,%2,%3}, {%4,%5,%6,%7}, {%8,%9}, {%0,%1,%2,%3};"
        : "+f"(c[0]), "+f"(c[1]), "+f"(c[2]), "+f"(c[3])
        : "r"(a[0]), "r"(a[1]), "r"(a[2]), "r"(a[3]), "r"(b[0]), "r"(b[1]));
}

// ----------------------------------------------------------------------------
// Kernel 0a: pre-round A = [hidden | z] -> g_A[m][4096], RN to fp16
// Each thread converts 8 floats -> 8 halves (one 16B store).
// ----------------------------------------------------------------------------
__global__ void __launch_bounds__(256)
preround_A(const float4* __restrict__ hidden, const float4* __restrict__ z) {
    size_t idx = (size_t)blockIdx.x * 256 + threadIdx.x;   // over M*512 groups
    size_t m = idx >> 9;
    int g = (int)(idx & 511);
    const float4* src = (g < 256) ? (hidden + m * 512 + g * 2)
                                  : (z + m * 512 + (g - 256) * 2);
    float4 v0 = src[0], v1 = src[1];
    __half2 h0 = __float22half2_rn(make_float2(v0.x, v0.y));
    __half2 h1 = __float22half2_rn(make_float2(v0.z, v0.w));
    __half2 h2 = __float22half2_rn(make_float2(v1.x, v1.y));
    __half2 h3 = __float22half2_rn(make_float2(v1.z, v1.w));
    uint4 o;
    o.x = *reinterpret_cast<uint32_t*>(&h0);
    o.y = *reinterpret_cast<uint32_t*>(&h1);
    o.z = *reinterpret_cast<uint32_t*>(&h2);
    o.w = *reinterpret_cast<uint32_t*>(&h3);
    reinterpret_cast<uint4*>(g_A)[idx] = o;
}

// ----------------------------------------------------------------------------
// Kernel 0b: pre-round B = [Ww ; Wz] -> g_B[k][1024], RN to fp16
// ----------------------------------------------------------------------------
__global__ void __launch_bounds__(256)
preround_B(const float4* __restrict__ Ww, const float4* __restrict__ Wz) {
    size_t idx = (size_t)blockIdx.x * 256 + threadIdx.x;   // over K_TOT*128 groups
    size_t k = idx >> 7;
    int g = (int)(idx & 127);
    const float4* src = (k < H2_DIM) ? (Ww + k * 256 + g * 2)
                                     : (Wz + (k - H2_DIM) * 256 + g * 2);
    float4 v0 = src[0], v1 = src[1];
    __half2 h0 = __float22half2_rn(make_float2(v0.x, v0.y));
    __half2 h1 = __float22half2_rn(make_float2(v0.z, v0.w));
    __half2 h2 = __float22half2_rn(make_float2(v1.x, v1.y));
    __half2 h3 = __float22half2_rn(make_float2(v1.z, v1.w));
    uint4 o;
    o.x = *reinterpret_cast<uint32_t*>(&h0);
    o.y = *reinterpret_cast<uint32_t*>(&h1);
    o.z = *reinterpret_cast<uint32_t*>(&h2);
    o.w = *reinterpret_cast<uint32_t*>(&h3);
    reinterpret_cast<uint4*>(g_B)[idx] = o;
}

// ----------------------------------------------------------------------------
// Stage fill: A tile [256 x 64]h, B tile [64 x 128]h; 256 threads, 8+4 cp.async
// ----------------------------------------------------------------------------
__device__ __forceinline__ void fill_stage(
    uint32_t smem_base, int slot, int kc, int mtile, int ntile, int tid)
{
    const int k0 = kc * KT;
    uint32_t aBase = smem_base + (uint32_t)(slot * STAGE_BYTES);
    uint32_t bBase = aBase + (uint32_t)(A_STAGE_HALVES * 2);

    // A: 256 rows x 8 chunks(16B = 8 halves) = 2048 chunks
    const __half* abase = g_A + k0;
#pragma unroll
    for (int i = 0; i < 8; i++) {
        int idx = tid + i * 256;
        int r = idx >> 3, g = idx & 7;
        const __half* src = abase + (size_t)(mtile * MT + r) * K_TOT + g * 8;
        uint32_t dst = aBase + (uint32_t)(r * A_STRIDE_H + g * 8) * 2u;
        cp_async16(dst, src);
    }
    // B: 64 rows x 16 chunks(16B) = 1024 chunks
    const __half* bbase = g_B + (size_t)k0 * V_DIM + ntile * NTILE;
#pragma unroll
    for (int i = 0; i < 4; i++) {
        int idx = tid + i * 256;
        int r = idx >> 4, c = idx & 15;
        const __half* src = bbase + (size_t)r * V_DIM + c * 8;
        uint32_t dst = bBase + (uint32_t)(r * B_STRIDE_H + c * 8) * 2u;
        cp_async16(dst, src);
    }
    CP_COMMIT_GROUP();
}

// ----------------------------------------------------------------------------
// Kernel 1: fused fp16 GEMM (mma.sync m16n8k16 + ldmatrix) + tanh-dot epilogue
// ----------------------------------------------------------------------------
__global__ void __launch_bounds__(256, 1)
dual_attn_gemm_kernel(const float* __restrict__ bw, const float* __restrict__ bz,
                      const float* __restrict__ Vw, const float* __restrict__ w_a)
{
    extern __shared__ char smem[];
    float* smemf = reinterpret_cast<float*>(smem);
    uint32_t smem_base = smem_u32(smem);
    const int tid  = threadIdx.x;
    const int wid  = tid >> 5;
    const int lane = tid & 31;
    const int ntile = blockIdx.x;   // 0..7 (fastest -> B resident in L2 per wave)
    const int mtile = blockIdx.y;   // 0..127

    const int warp_m = wid & 3;     // 64-row slab
    const int warp_n = wid >> 2;    // 64-col slab

    // ldmatrix quadrant mapping (q = lane/8)
    const int q = lane >> 3;
    const int lrow = lane & 7;
    // A (non-trans): q0=(r0-7,k0-7) q1=(r8-15,k0-7) q2=(r0-7,k8-15) q3=(r8-15,k8-15)
    const uint32_t aLaneOff =
        (uint32_t)(((warp_m * 64 + (q & 1) * 8 + lrow) * A_STRIDE_H + (q >> 1) * 8) * 2);
    // B (trans): q0=(k0-7, tile j) q1=(k8-15, tile j) q2=(k0-7, tile j+1) q3=(k8-15, tile j+1)
    const uint32_t bLaneOff =
        (uint32_t)((((q & 1) * 8 + lrow) * B_STRIDE_H + warp_n * 64 + (q >> 1) * 8) * 2);

    float* biasS = reinterpret_cast<float*>(smem + BIAS_OFF_B);
    float* vwS   = reinterpret_cast<float*>(smem + VW_OFF_B);
    {
        float wa = __ldg(w_a) * ALPHA_S;   // inside tanh: NOT shift-invariant
        if (tid < 128) {
            int n = ntile * NTILE + tid;
            biasS[tid] = bw[n] + bz[n] + wa;
            vwS[tid]   = Vw[n];
        }
    }

    float acc[4][8][4];
#pragma unroll
    for (int i = 0; i < 4; i++)
#pragma unroll
        for (int j = 0; j < 8; j++)
#pragma unroll
            for (int t = 0; t < 4; t++)
                acc[i][j][t] = 0.0f;

    fill_stage(smem_base, 0, 0, mtile, ntile, tid);
    fill_stage(smem_base, 1, 1, mtile, ntile, tid);

    for (int kc = 0; kc < NCHUNK; kc++) {
        if (kc + 2 < NCHUNK) {
            fill_stage(smem_base, (kc + 2) % STAGES, kc + 2, mtile, ntile, tid);
            CP_WAIT_GROUP(2);
        } else if (kc + 2 == NCHUNK) {
            CP_WAIT_GROUP(1);
        } else {
            CP_WAIT_GROUP(0);
        }
        __syncthreads();

        const int slot = kc % STAGES;
        const uint32_t aStage = smem_base + (uint32_t)(slot * STAGE_BYTES);
        const uint32_t bStage = aStage + (uint32_t)(A_STAGE_HALVES * 2);

        uint32_t a[2][4][4];
        uint32_t b[2][8][2];

        // preload ks=0 fragments
#pragma unroll
        for (int i = 0; i < 4; i++)
            ldsm_x4(a[0][i], aStage + aLaneOff + (uint32_t)(i * 16 * A_STRIDE_H * 2));
#pragma unroll
        for (int p = 0; p < 4; p++)
            ldsm_x4_trans(b[0][2 * p][0], b[0][2 * p][1],
                          b[0][2 * p + 1][0], b[0][2 * p + 1][1],
                          bStage + bLaneOff + (uint32_t)(p * 16 * 2));

#pragma unroll
        for (int ks = 0; ks < KT / 16; ks++) {
            const int cur = ks & 1;
            const int nxt = cur ^ 1;
            if (ks < KT / 16 - 1) {
                // prefetch ks+1 fragments; latency hides under the 32 MMAs below
#pragma unroll
                for (int i = 0; i < 4; i++)
                    ldsm_x4(a[nxt][i],
                            aStage + aLaneOff +
                            (uint32_t)((i * 16 * A_STRIDE_H + (ks + 1) * 16) * 2));
                uint32_t bks = bStage + bLaneOff + (uint32_t)((ks + 1) * 16 * B_STRIDE_H * 2);
#pragma unroll
                for (int p = 0; p < 4; p++)
                    ldsm_x4_trans(b[nxt][2 * p][0], b[nxt][2 * p][1],
                                  b[nxt][2 * p + 1][0], b[nxt][2 * p + 1][1],
                                  bks + (uint32_t)(p * 16 * 2));
            }
#pragma unroll
            for (int i = 0; i < 4; i++)
#pragma unroll
                for (int j = 0; j < 8; j++)
                    mma_f16(acc[i][j], a[cur][i], b[cur][j]);
        }
        __syncthreads();
    }

    // ---- Epilogue: acc -> SMEM overlay (256 x 136 fp32), tanh-dot with Vw ----
    float* Cs = smemf;   // 256*136*4 = 139264 B <= stage area (162816 B)
    {
        int gr = lane >> 2, gc = lane & 3;
#pragma unroll
        for (int i = 0; i < 4; i++) {
            int r0 = warp_m * 64 + i * 16 + gr;
#pragma unroll
            for (int j = 0; j < 8; j++) {
                int c0 = warp_n * 64 + j * 8 + 2 * gc;
                *reinterpret_cast<float2*>(Cs + r0 * C_STRIDE + c0) =
                    make_float2(acc[i][j][0], acc[i][j][1]);
                *reinterpret_cast<float2*>(Cs + (r0 + 8) * C_STRIDE + c0) =
                    make_float2(acc[i][j][2], acc[i][j][3]);
            }
        }
    }
    __syncthreads();

    // 256 threads: one row each, sum 128 columns
    {
        const float* crow = Cs + tid * C_STRIDE;
        float acc_u = 0.0f;
#pragma unroll 8
        for (int c = 0; c < NTILE; c++) {
            float x = crow[c] + biasS[c];
            float e = __expf(2.0f * x);
            float t = 1.0f - 2.0f / (e + 1.0f);   // tanh(x)
            acc_u += t * vwS[c];
        }
        g_part[(size_t)ntile * M_DIM + mtile * MT + tid] = acc_u;
    }
}

// ----------------------------------------------------------------------------
// Kernel 2: softmax over sequence dim (one block per batch column)
// ----------------------------------------------------------------------------
__global__ void __launch_bounds__(1024)
softmax_kernel(float* __restrict__ out) {
    int b = blockIdx.x;      // 0..15
    int tid = threadIdx.x;   // 0..1023
    __shared__ float red[1024];

    float u[2];
    float lmax = -1e30f;
#pragma unroll
    for (int i = 0; i < 2; i++) {
        int s = tid + i * 1024;
        size_t m = (size_t)s * B_DIM + b;
        float v = 0.0f;
#pragma unroll
        for (int t = 0; t < NTILES; t++)
            v += g_part[(size_t)t * M_DIM + m];
        u[i] = v;
        lmax = fmaxf(lmax, v);
    }
    red[tid] = lmax;
    __syncthreads();
    for (int off = 512; off > 0; off >>= 1) {
        if (tid < off) red[tid] = fmaxf(red[tid], red[tid + off]);
        __syncthreads();
    }
    float gmax = red[0];
    __syncthreads();

    float lsum = 0.0f;
#pragma unroll
    for (int i = 0; i < 2; i++) {
        u[i] = __expf(u[i] - gmax);
        lsum += u[i];
    }
    red[tid] = lsum;
    __syncthreads();
    for (int off = 512; off > 0; off >>= 1) {
        if (tid < off) red[tid] += red[tid + off];
        __syncthreads();
    }
    float inv = 1.0f / red[0];
#pragma unroll
    for (int i = 0; i < 2; i++) {
        int s = tid + i * 1024;
        out[(size_t)s * B_DIM + b] = u[i] * inv;
    }
}

// ----------------------------------------------------------------------------
// Launch
// ----------------------------------------------------------------------------
extern "C" void kernel_launch(void* const* d_in, const int* in_sizes, int n_in,
                              void* d_out, int out_size) {
    (void)in_sizes; (void)n_in; (void)out_size;
    const float* hidden = (const float*)d_in[0];
    const float* z      = (const float*)d_in[1];
    const float* Ww     = (const float*)d_in[2];
    const float* bw     = (const float*)d_in[3];
    const float* Wz     = (const float*)d_in[4];
    const float* bz     = (const float*)d_in[5];
    const float* Vw     = (const float*)d_in[6];
    // d_in[7] = vb (softmax-shift-invariant, unused)
    const float* w_a    = (const float*)d_in[8];
    float* out = (float*)d_out;

    static int smem_set = 0;
    if (!smem_set) {
        cudaFuncSetAttribute(dual_attn_gemm_kernel,
                             cudaFuncAttributeMaxDynamicSharedMemorySize, SMEM_BYTES);
        smem_set = 1;
    }

    // Pre-round inputs to fp16 (RN; 11-bit mantissa = tf32-equivalent precision)
    preround_A<<<(int)(((size_t)M_DIM * 512) / 256), 256>>>(
        (const float4*)hidden, (const float4*)z);
    preround_B<<<(int)(((size_t)K_TOT * 128) / 256), 256>>>(
        (const float4*)Ww, (const float4*)Wz);

    dual_attn_gemm_kernel<<<dim3(NTILES, MTILES), 256, SMEM_BYTES>>>(bw, bz, Vw, w_a);
    softmax_kernel<<<B_DIM, 1024>>>(out);
}